// round 16
// baseline (speedup 1.0000x reference)
#include <cuda_runtime.h>
#include <cstdint>

// Hierarchical softmax CE — segment-per-thread (3x warps) + 256-bit
// L2::evict_last pinned loads (R15 mechanism). Warm graph replays hit the
// pinned ~30MB in L2 (~240cyc) instead of DRAM (~700cyc); at L2-hit latency
// the in-flight pool turns over 3x faster, so 3x thread parallelism is what
// converts that into throughput.
// OFFSET=[0,10,110,1110]; groups = 10 contiguous even-based nodes.
// target l: bases {0, 10+10*(l/100), 110+10*(l/10)}, sel {l/100,(l/10)%10,l%10}.

#define BATCH    65536
#define NNODES   1110
#define TPB      128
#define RBLOCKS  (BATCH / TPB)      // 512 row-blocks
#define NBLOCKS  (3 * RBLOCKS)      // 1536 (segment-per-thread)
#define FIN      (NBLOCKS / TPB)    // 12

__device__ float    g_partials[NBLOCKS];
__device__ unsigned g_ticket = 0;

__device__ __forceinline__ void ld_el_8(const float* p, float* v) {
    unsigned r0, r1, r2, r3, r4, r5, r6, r7;
    asm("ld.global.L2::evict_last.v8.b32 {%0,%1,%2,%3,%4,%5,%6,%7}, [%8];"
        : "=r"(r0), "=r"(r1), "=r"(r2), "=r"(r3),
          "=r"(r4), "=r"(r5), "=r"(r6), "=r"(r7)
        : "l"(p));
    v[0] = __uint_as_float(r0); v[1] = __uint_as_float(r1);
    v[2] = __uint_as_float(r2); v[3] = __uint_as_float(r3);
    v[4] = __uint_as_float(r4); v[5] = __uint_as_float(r5);
    v[6] = __uint_as_float(r6); v[7] = __uint_as_float(r7);
}

__global__ void __launch_bounds__(TPB)
hsm_r16_kernel(const float* __restrict__ x,
               const float* __restrict__ w,
               const int* __restrict__ target,
               float* __restrict__ out) {
    const int tid = threadIdx.x;
    const int seg = blockIdx.x / RBLOCKS;            // 0,1,2 — uniform per block
    const int row = (blockIdx.x % RBLOCKS) * TPB + tid;

    const int l  = __ldg(target + row);              // coalesced
    const int j  = l / 10;
    const int a0 = l / 100;

    int base, loc;
    if (seg == 0)      { base = 0;            loc = a0; }
    else if (seg == 1) { base = 10 + 10 * a0; loc = j - 10 * a0; }
    else               { base = 110 + 10 * j; loc = l - 10 * j; }

    const size_t abs = (size_t)row * NNODES + base;  // even
    const int d = (int)(abs & 7);                    // 0,2,4,6 ; d+10 <= 16
    const float* p = x + (abs & ~(size_t)7);         // 32B-aligned window

    float v[16];
    ld_el_8(p,     &v[0]);                           // two pinned 32B loads
    ld_el_8(p + 8, &v[8]);

    const float NEG = -3.0e38f;
    float s = 0.0f;
#pragma unroll
    for (int i = 0; i < 16; i++) {
        float vi = (i >= d && i < d + 10) ? v[i] : NEG;
        s += __expf(vi);                             // masked -> exact 0
    }
    const int sel = d + loc;
    float xv = v[0];
#pragma unroll
    for (int i = 1; i < 16; i++) xv = (sel == i) ? v[i] : xv;

    float acc = __ldg(w + base + loc) * (xv - __logf(s));

    // ---- deterministic block reduction ----
    __shared__ float sm[TPB];
    sm[tid] = acc;
    __syncthreads();
#pragma unroll
    for (int s2 = TPB / 2; s2 > 32; s2 >>= 1) {
        if (tid < s2) sm[tid] += sm[tid + s2];
        __syncthreads();
    }
    __shared__ bool s_last;
    if (tid < 32) {
        float vv = sm[tid] + sm[tid + 32];
#pragma unroll
        for (int o = 16; o > 0; o >>= 1)
            vv += __shfl_down_sync(0xFFFFFFFFu, vv, o);
        if (tid == 0) {
            g_partials[blockIdx.x] = vv;
            __threadfence();
            unsigned t = atomicAdd(&g_ticket, 1u);
            s_last = (t == NBLOCKS - 1);
        }
    }
    __syncthreads();

    // ---- last block: deterministic fixed-order sum of 1536 partials ----
    if (s_last) {
        float vv = 0.0f;
#pragma unroll
        for (int kk = 0; kk < FIN; kk++)             // 12 per thread, fixed order
            vv += g_partials[tid + kk * TPB];
        sm[tid] = vv;
        __syncthreads();
#pragma unroll
        for (int s2 = TPB / 2; s2 > 32; s2 >>= 1) {
            if (tid < s2) sm[tid] += sm[tid + s2];
            __syncthreads();
        }
        if (tid < 32) {
            float r = sm[tid] + sm[tid + 32];
#pragma unroll
            for (int o = 16; o > 0; o >>= 1)
                r += __shfl_down_sync(0xFFFFFFFFu, r, o);
            if (tid == 0) {
                out[0] = -r / (float)BATCH;
                g_ticket = 0;                         // reset for next graph replay
            }
        }
    }
}

extern "C" void kernel_launch(void* const* d_in, const int* in_sizes, int n_in,
                              void* d_out, int out_size) {
    const float* x      = (const float*)d_in[0];
    const float* w      = (const float*)d_in[1];
    const int*   target = (const int*)d_in[2];
    float* out = (float*)d_out;

    hsm_r16_kernel<<<NBLOCKS, TPB>>>(x, w, target, out);
}

// round 17
// speedup vs baseline: 1.0590x; 1.0590x over previous
#include <cuda_runtime.h>
#include <cstdint>

// Hierarchical softmax CE — R15 gather (2x 256-bit L2::evict_last sector-exact
// loads per segment) + single-atomic fixed-point finish (no partials array,
// no second reduction phase). Integer atomics commute exactly -> deterministic.
// OFFSET=[0,10,110,1110]; groups = 10 contiguous even-based nodes.
// target l: bases {0, 10+10*(l/100), 110+10*(l/10)}, sel {l/100,(l/10)%10,l%10}.

#define BATCH   65536
#define NNODES  1110
#define TPB     128
#define NBLOCKS (BATCH / TPB)   // 512
#define FP_SCALE 4294967296.0   // 2^32

__device__ unsigned long long g_acc    = 0ull;
__device__ unsigned           g_ticket = 0;

__device__ __forceinline__ void ld_el_8(const float* p, float* v) {
    unsigned r0, r1, r2, r3, r4, r5, r6, r7;
    asm("ld.global.L2::evict_last.v8.b32 {%0,%1,%2,%3,%4,%5,%6,%7}, [%8];"
        : "=r"(r0), "=r"(r1), "=r"(r2), "=r"(r3),
          "=r"(r4), "=r"(r5), "=r"(r6), "=r"(r7)
        : "l"(p));
    v[0] = __uint_as_float(r0); v[1] = __uint_as_float(r1);
    v[2] = __uint_as_float(r2); v[3] = __uint_as_float(r3);
    v[4] = __uint_as_float(r4); v[5] = __uint_as_float(r5);
    v[6] = __uint_as_float(r6); v[7] = __uint_as_float(r7);
}

__global__ void __launch_bounds__(TPB)
hsm_r17_kernel(const float* __restrict__ x,
               const float* __restrict__ w,
               const int* __restrict__ target,
               float* __restrict__ out) {
    const int tid = threadIdx.x;
    const int row = blockIdx.x * TPB + tid;

    const int l  = __ldg(target + row);
    const int j  = l / 10;
    const int a0 = l / 100;
    const int bases[3] = {0, 10 + 10 * a0, 110 + 10 * j};
    const int locs[3]  = {a0, j - 10 * a0, l - 10 * j};

    const size_t rowoff = (size_t)row * NNODES;

    // ---- 6 pinned sector-exact loads, all in flight ----
    float v[3][16];
    int dd[3];
#pragma unroll
    for (int s3 = 0; s3 < 3; s3++) {
        const size_t abs = rowoff + bases[s3];       // even
        dd[s3] = (int)(abs & 7);                     // 0,2,4,6 ; d+10 <= 16
        const float* p = x + (abs & ~(size_t)7);     // 32B-aligned window
        ld_el_8(p,     &v[s3][0]);
        ld_el_8(p + 8, &v[s3][8]);
    }

    const float NEG = -3.0e38f;
    float acc = 0.0f;
#pragma unroll
    for (int s3 = 0; s3 < 3; s3++) {
        const int d = dd[s3];                        // valid window: [d, d+10)
        float s = 0.0f;
#pragma unroll
        for (int i = 0; i < 16; i++) {
            float vi = (i >= d && i < d + 10) ? v[s3][i] : NEG;
            s += __expf(vi);                         // masked -> exact 0
        }
        const int sel = d + locs[s3];
        float xv = v[s3][0];
#pragma unroll
        for (int i = 1; i < 16; i++) xv = (sel == i) ? v[s3][i] : xv;
        acc += __ldg(w + bases[s3] + locs[s3]) * (xv - __logf(s));
    }

    // ---- deterministic block reduction (smem tree + warp shuffle) ----
    __shared__ float sm[TPB];
    sm[tid] = acc;
    __syncthreads();
#pragma unroll
    for (int s = TPB / 2; s > 32; s >>= 1) {
        if (tid < s) sm[tid] += sm[tid + s];
        __syncthreads();
    }
    if (tid < 32) {
        float bv = sm[tid] + sm[tid + 32];
#pragma unroll
        for (int o = 16; o > 0; o >>= 1)
            bv += __shfl_down_sync(0xFFFFFFFFu, bv, o);
        if (tid == 0) {
            // fixed-point add: exactly commutative -> bit-deterministic total
            long long q = llrint((double)bv * FP_SCALE);
            atomicAdd(&g_acc, (unsigned long long)q);
            __threadfence();
            unsigned t = atomicAdd(&g_ticket, 1u);
            if (t == NBLOCKS - 1) {                  // last arrival finishes
                unsigned long long tot = atomicAdd(&g_acc, 0ull);  // all adds visible
                double total = (double)(long long)tot / FP_SCALE;
                out[0] = (float)(-total / (double)BATCH);
                g_acc    = 0ull;                      // reset for next graph replay
                g_ticket = 0;
            }
        }
    }
}

extern "C" void kernel_launch(void* const* d_in, const int* in_sizes, int n_in,
                              void* d_out, int out_size) {
    const float* x      = (const float*)d_in[0];
    const float* w      = (const float*)d_in[1];
    const int*   target = (const int*)d_in[2];
    float* out = (float*)d_out;

    hsm_r17_kernel<<<NBLOCKS, TPB>>>(x, w, target, out);
}